// round 14
// baseline (speedup 1.0000x reference)
#include <cuda_runtime.h>
#include <cstdint>
#include <cstddef>

typedef unsigned long long ull;

#define THREADS 512
#define TM      128
#define KD      64
#define H       100
#define HP      128
#define NOUT    384
#define SXS     68    // x row stride
#define SH      100   // h row stride
#define SY      68    // y1 staging stride

// shared memory float offsets
#define OFF_H1   0                    // 128*100 = 12800 (dead after GEMM B -> SY1)
#define OFF_H2   12800                // 12800
#define OFF_W4   25600                // 100*128 = 12800
#define OFF_POOL 38400                // pool
#define OFF_X    OFF_POOL             // 128*68 = 8704   (phase A)
#define OFF_W1   (OFF_POOL + 8704)    // 64*128 = 8192   (phase A)
#define OFF_W2B  OFF_POOL             // 2 x 7680 = 15360 (phase C dbuf)
#define OFF_SY1  OFF_H1               // 128*68 = 8704   (epilogue)
#define OFF_B1   55296                // 128
#define OFF_B4   55424                // 128
#define OFF_B2   55552                // 384 (permuted)
#define SM_FLOATS 55936
#define SMEM_BYTES (SM_FLOATS * 4)    // 223744

__device__ __forceinline__ ull pk2(float lo, float hi) {
    ull r; asm("mov.b64 %0,{%1,%2};" : "=l"(r) : "f"(lo), "f"(hi)); return r;
}
__device__ __forceinline__ void upk2(ull v, float& lo, float& hi) {
    asm("mov.b64 {%0,%1},%2;" : "=f"(lo), "=f"(hi) : "l"(v));
}
__device__ __forceinline__ ull ffma2(ull a, ull b, ull c) {
    ull d; asm("fma.rn.f32x2 %0,%1,%2,%3;" : "=l"(d) : "l"(a), "l"(b), "l"(c)); return d;
}
__device__ __forceinline__ void upk4(ulonglong2 v, float* o) {
    upk2(v.x, o[0], o[1]); upk2(v.y, o[2], o[3]);
}

__device__ __forceinline__ void cp16(uint32_t dst, const void* src) {
    asm volatile("cp.async.cg.shared.global [%0], [%1], 16;" :: "r"(dst), "l"(src));
}
#define CP_COMMIT() asm volatile("cp.async.commit_group;")
#define CP_WAIT(n)  asm volatile("cp.async.wait_group %0;" :: "n"(n))

// accurate exp, fast-math-proof (no MUFU)
__device__ __forceinline__ float my_expf(float z) {
    float kf = rintf(z * 1.4426950408889634f);
    float r  = fmaf(kf, -0.693145751953125f, z);
    r        = fmaf(kf, -1.42860677e-6f,     r);
    float p  = 1.9841270e-4f;
    p = fmaf(p, r, 1.3888889e-3f);
    p = fmaf(p, r, 8.3333338e-3f);
    p = fmaf(p, r, 4.1666668e-2f);
    p = fmaf(p, r, 1.6666667e-1f);
    p = fmaf(p, r, 0.5f);
    p = fmaf(p, r, 1.0f);
    p = fmaf(p, r, 1.0f);
    int ik = (int)kf;
    return p * __int_as_float((ik + 127) << 23);
}
__device__ __forceinline__ float my_tanhf(float x) {
    float ax = fminf(fabsf(x), 10.0f);
    float e  = my_expf(2.0f * ax);
    float rc = __frcp_rn(e + 1.0f);
    float th = fmaf(-2.0f, rc, 1.0f);
    return (x < 0.0f) ? -th : th;
}

// GEMM-C permuted column index: warp w owns [24w,24w+24) =
//   y1 cols 4w..4w+3, then y2 cols 20w..20w+19 (4 full segments, in order)
__device__ __forceinline__ int permC(int c) {
    if (c < KD) return (c >> 2) * 24 + (c & 3);
    int cc = c - KD;
    return (cc / 20) * 24 + 4 + (cc % 20);
}

// one-hot argmax of 5 logits v[]+g[] -> o[0..4]
__device__ __forceinline__ void seg_onehot(const float* v, const float* g, float* o) {
    float best = v[0] + g[0];
    int arg = 0;
#pragma unroll
    for (int m = 1; m < 5; m++) {
        float val = v[m] + g[m];
        if (val > best) { best = val; arg = m; }
    }
#pragma unroll
    for (int m = 0; m < 5; m++) o[m] = (m == arg) ? 1.0f : 0.0f;
}

__global__ void __launch_bounds__(THREADS, 1)
fused_mlp_gumbel(const float* __restrict__ x,  const float* __restrict__ W1,
                 const float* __restrict__ b1, const float* __restrict__ W4,
                 const float* __restrict__ b4, const float* __restrict__ W2,
                 const float* __restrict__ b2, const float* __restrict__ gum,
                 float* __restrict__ out)
{
    extern __shared__ float sm[];
    const int tid  = threadIdx.x;
    const int warp = tid >> 5;
    const int lane = tid & 31;
    const int row0 = blockIdx.x * TM;
    const uint32_t smb = (uint32_t)__cvta_generic_to_shared(sm);

    // ---- group0: x tile + W1 via cp.async ----
    {
        const float4* xg = (const float4*)(x + (size_t)row0 * KD);
        for (int i = tid; i < TM * KD / 4; i += THREADS) {
            int r = i >> 4, c = i & 15;
            cp16(smb + (uint32_t)(OFF_X + r * SXS + c * 4) * 4, xg + i);
        }
        for (int i = tid; i < KD * 25; i += THREADS) {
            int k = i / 25, c = i - k * 25;
            cp16(smb + (uint32_t)(OFF_W1 + k * HP + c * 4) * 4, W1 + k * H + c * 4);
        }
    }
    CP_COMMIT();
    // ---- group1: W4 via cp.async (consumed after GEMM A) ----
    for (int i = tid; i < H * 25; i += THREADS) {
        int k = i / 25, c = i - k * 25;
        cp16(smb + (uint32_t)(OFF_W4 + k * HP + c * 4) * 4, W4 + k * H + c * 4);
    }
    CP_COMMIT();

    // ---- zero pads + biases (plain stores, disjoint bytes from cp.async dsts) ----
    for (int i = tid; i < KD * (HP - H); i += THREADS) {
        int k = i / 28, c = H + (i - k * 28);
        sm[OFF_W1 + k * HP + c] = 0.0f;
    }
    for (int i = tid; i < H * (HP - H); i += THREADS) {
        int k = i / 28, c = H + (i - k * 28);
        sm[OFF_W4 + k * HP + c] = 0.0f;
    }
    for (int i = tid; i < HP; i += THREADS) {
        sm[OFF_B1 + i] = (i < H) ? b1[i] : 0.0f;
        sm[OFF_B4 + i] = (i < H) ? b4[i] : 0.0f;
    }
    for (int i = tid; i < NOUT; i += THREADS) sm[OFF_B2 + permC(i)] = b2[i];

    CP_WAIT(1);          // x + W1 landed (W4 may still be in flight)
    __syncthreads();

    // ---- GEMM A: h1 = tanh(x @ W1 + b1), 4 rows x 8 cols per thread ----
    {
        const int c0 = warp * 8;
        ulonglong2 b01 = *(const ulonglong2*)(sm + OFF_B1 + c0);
        ulonglong2 b23 = *(const ulonglong2*)(sm + OFF_B1 + c0 + 4);
        ulonglong2 a[4][2];
#pragma unroll
        for (int r = 0; r < 4; r++) { a[r][0] = b01; a[r][1] = b23; }
        const float* xr[4];
#pragma unroll
        for (int r = 0; r < 4; r++) xr[r] = sm + OFF_X + (lane + 32 * r) * SXS;
#pragma unroll 4
        for (int k4 = 0; k4 < KD; k4 += 4) {
            float hv[4][4];
#pragma unroll
            for (int r = 0; r < 4; r++) {
                float4 t = *(const float4*)(xr[r] + k4);
                hv[r][0] = t.x; hv[r][1] = t.y; hv[r][2] = t.z; hv[r][3] = t.w;
            }
#pragma unroll
            for (int q = 0; q < 4; q++) {
                const ulonglong2* wp = (const ulonglong2*)(sm + OFF_W1 + (k4 + q) * HP + c0);
                ulonglong2 w0 = wp[0], w1 = wp[1];
#pragma unroll
                for (int r = 0; r < 4; r++) {
                    ull xa = pk2(hv[r][q], hv[r][q]);
                    a[r][0].x = ffma2(xa, w0.x, a[r][0].x);
                    a[r][0].y = ffma2(xa, w0.y, a[r][0].y);
                    a[r][1].x = ffma2(xa, w1.x, a[r][1].x);
                    a[r][1].y = ffma2(xa, w1.y, a[r][1].y);
                }
            }
        }
#pragma unroll
        for (int r = 0; r < 4; r++) {
            float v[8]; upk4(a[r][0], v); upk4(a[r][1], v + 4);
            float* hp = sm + OFF_H1 + (lane + 32 * r) * SH + c0;
            if (c0 + 8 <= H) {
                float4 lo = {my_tanhf(v[0]), my_tanhf(v[1]), my_tanhf(v[2]), my_tanhf(v[3])};
                float4 hi = {my_tanhf(v[4]), my_tanhf(v[5]), my_tanhf(v[6]), my_tanhf(v[7])};
                *(float4*)hp = lo; *(float4*)(hp + 4) = hi;
            } else if (c0 < H) {
                float4 lo = {my_tanhf(v[0]), my_tanhf(v[1]), my_tanhf(v[2]), my_tanhf(v[3])};
                *(float4*)hp = lo;
            }
        }
    }
    CP_WAIT(0);          // W4 landed
    __syncthreads();     // h1 visible; X/W1 region dead

    // ---- issue W2 chunk 0 -> buf0 (permuted 16B blocks), in flight during GEMM B ----
    for (int i = tid; i < 1920; i += THREADS) {
        int k = i / 96, c4 = (i - k * 96) * 4;
        int p = permC(c4);
        cp16(smb + (uint32_t)(OFF_W2B + k * NOUT + p) * 4, W2 + (size_t)k * NOUT + c4);
    }
    CP_COMMIT();

    // ---- GEMM B: h2 = tanh(h1 @ W4 + b4) ----
    {
        const int c0 = warp * 8;
        ulonglong2 b01 = *(const ulonglong2*)(sm + OFF_B4 + c0);
        ulonglong2 b23 = *(const ulonglong2*)(sm + OFF_B4 + c0 + 4);
        ulonglong2 a[4][2];
#pragma unroll
        for (int r = 0; r < 4; r++) { a[r][0] = b01; a[r][1] = b23; }
        const float* hr[4];
#pragma unroll
        for (int r = 0; r < 4; r++) hr[r] = sm + OFF_H1 + (lane + 32 * r) * SH;
#pragma unroll 5
        for (int k4 = 0; k4 < H; k4 += 4) {
            float hv[4][4];
#pragma unroll
            for (int r = 0; r < 4; r++) {
                float4 t = *(const float4*)(hr[r] + k4);
                hv[r][0] = t.x; hv[r][1] = t.y; hv[r][2] = t.z; hv[r][3] = t.w;
            }
#pragma unroll
            for (int q = 0; q < 4; q++) {
                const ulonglong2* wp = (const ulonglong2*)(sm + OFF_W4 + (k4 + q) * HP + c0);
                ulonglong2 w0 = wp[0], w1 = wp[1];
#pragma unroll
                for (int r = 0; r < 4; r++) {
                    ull xa = pk2(hv[r][q], hv[r][q]);
                    a[r][0].x = ffma2(xa, w0.x, a[r][0].x);
                    a[r][0].y = ffma2(xa, w0.y, a[r][0].y);
                    a[r][1].x = ffma2(xa, w1.x, a[r][1].x);
                    a[r][1].y = ffma2(xa, w1.y, a[r][1].y);
                }
            }
        }
#pragma unroll
        for (int r = 0; r < 4; r++) {
            float v[8]; upk4(a[r][0], v); upk4(a[r][1], v + 4);
            float* hp = sm + OFF_H2 + (lane + 32 * r) * SH + c0;
            if (c0 + 8 <= H) {
                float4 lo = {my_tanhf(v[0]), my_tanhf(v[1]), my_tanhf(v[2]), my_tanhf(v[3])};
                float4 hi = {my_tanhf(v[4]), my_tanhf(v[5]), my_tanhf(v[6]), my_tanhf(v[7])};
                *(float4*)hp = lo; *(float4*)(hp + 4) = hi;
            } else if (c0 < H) {
                float4 lo = {my_tanhf(v[0]), my_tanhf(v[1]), my_tanhf(v[2]), my_tanhf(v[3])};
                *(float4*)hp = lo;
            }
        }
    }
    CP_WAIT(0);          // chunk0 landed
    __syncthreads();     // h2 visible; H1 region dead

    // =====================================================================
    // GEMM C pass 0: perm cols cw..cw+13 = 4 y1 cols + segments 0,1
    // =====================================================================
    const int cw = warp * 24;
    {
        ulonglong2 A[4][3]; ull Ax[4];
        {
            const float* bb = sm + OFF_B2 + cw;
            ulonglong2 c0v = *(const ulonglong2*)bb;
            ulonglong2 c1v = *(const ulonglong2*)(bb + 4);
            ulonglong2 c2v = *(const ulonglong2*)(bb + 8);
            ull cxv = *(const ull*)(bb + 12);
#pragma unroll
            for (int r = 0; r < 4; r++) { A[r][0] = c0v; A[r][1] = c1v; A[r][2] = c2v; Ax[r] = cxv; }
        }
#pragma unroll 1
        for (int ch = 0; ch < 5; ch++) {
            int gi = ch, buf = gi & 1;
            {   // prefetch next chunk (always exists for gi<9)
                int nch = (gi + 1) % 5, nbuf = (gi + 1) & 1;
                for (int i = tid; i < 1920; i += THREADS) {
                    int k = i / 96, c4 = (i - k * 96) * 4;
                    int p = permC(c4);
                    cp16(smb + (uint32_t)(OFF_W2B + nbuf * 7680 + k * NOUT + p) * 4,
                         W2 + (size_t)(nch * 20 + k) * NOUT + c4);
                }
                CP_COMMIT();
            }
            const float* wb = sm + OFF_W2B + buf * 7680;
            const float* hr[4];
#pragma unroll
            for (int r = 0; r < 4; r++)
                hr[r] = sm + OFF_H2 + (lane + 32 * r) * SH + ch * 20;
#pragma unroll
            for (int kq = 0; kq < 20; kq += 4) {
                float hv[4][4];
#pragma unroll
                for (int r = 0; r < 4; r++) {
                    float4 t = *(const float4*)(hr[r] + kq);
                    hv[r][0] = t.x; hv[r][1] = t.y; hv[r][2] = t.z; hv[r][3] = t.w;
                }
#pragma unroll
                for (int q = 0; q < 4; q++) {
                    const float* wrow = wb + (kq + q) * NOUT + cw;
                    ulonglong2 w0 = *(const ulonglong2*)wrow;
                    ulonglong2 w1 = *(const ulonglong2*)(wrow + 4);
                    ulonglong2 w2 = *(const ulonglong2*)(wrow + 8);
                    ull wx = *(const ull*)(wrow + 12);
#pragma unroll
                    for (int r = 0; r < 4; r++) {
                        ull xa = pk2(hv[r][q], hv[r][q]);
                        A[r][0].x = ffma2(xa, w0.x, A[r][0].x);
                        A[r][0].y = ffma2(xa, w0.y, A[r][0].y);
                        A[r][1].x = ffma2(xa, w1.x, A[r][1].x);
                        A[r][1].y = ffma2(xa, w1.y, A[r][1].y);
                        A[r][2].x = ffma2(xa, w2.x, A[r][2].x);
                        A[r][2].y = ffma2(xa, w2.y, A[r][2].y);
                        Ax[r]     = ffma2(xa, wx,   Ax[r]);
                    }
                }
            }
            CP_WAIT(0);
            __syncthreads();
        }
        // pass-0 epilogue: y1 logits -> smem; segments 0,1 -> one-hot -> global
#pragma unroll
        for (int r = 0; r < 4; r++) {
            float v[14];
            upk4(A[r][0], v); upk4(A[r][1], v + 4); upk4(A[r][2], v + 8);
            upk2(Ax[r], v[12], v[13]);
            int row = lane + 32 * r;
            float4 s0 = {v[0], v[1], v[2], v[3]};
            *(float4*)(sm + OFF_SY1 + row * SY + warp * 4) = s0;

            const float* g = gum + (size_t)(row0 + row) * (KD * 5) + warp * 20;
            float4 g0 = *(const float4*)g;
            float4 g1 = *(const float4*)(g + 4);
            float2 g2 = *(const float2*)(g + 8);
            float gf[10] = {g0.x, g0.y, g0.z, g0.w, g1.x, g1.y, g1.z, g1.w, g2.x, g2.y};
            float ov[10];
            seg_onehot(v + 4, gf,     ov);
            seg_onehot(v + 9, gf + 5, ov + 5);
            float* op = out + (size_t)(row0 + row) * NOUT + KD + warp * 20;
            float4 o0 = {ov[0], ov[1], ov[2], ov[3]};
            float4 o1 = {ov[4], ov[5], ov[6], ov[7]};
            float2 o2 = {ov[8], ov[9]};
            *(float4*)op = o0;
            *(float4*)(op + 4) = o1;
            *(float2*)(op + 8) = o2;
        }
    }

    // =====================================================================
    // GEMM C pass 1: perm cols cw+14..cw+23 = segments 2,3
    // =====================================================================
    {
        ull By[4]; ulonglong2 B[4][2];
        {
            const float* bb = sm + OFF_B2 + cw;
            ull cyv = *(const ull*)(bb + 14);
            ulonglong2 c3v = *(const ulonglong2*)(bb + 16);
            ulonglong2 c4v = *(const ulonglong2*)(bb + 20);
#pragma unroll
            for (int r = 0; r < 4; r++) { By[r] = cyv; B[r][0] = c3v; B[r][1] = c4v; }
        }
#pragma unroll 1
        for (int ch = 0; ch < 5; ch++) {
            int gi = 5 + ch, buf = gi & 1;
            if (gi < 9) {
                int nch = (gi + 1) % 5, nbuf = (gi + 1) & 1;
                for (int i = tid; i < 1920; i += THREADS) {
                    int k = i / 96, c4 = (i - k * 96) * 4;
                    int p = permC(c4);
                    cp16(smb + (uint32_t)(OFF_W2B + nbuf * 7680 + k * NOUT + p) * 4,
                         W2 + (size_t)(nch * 20 + k) * NOUT + c4);
                }
                CP_COMMIT();
            }
            const float* wb = sm + OFF_W2B + buf * 7680;
            const float* hr[4];
#pragma unroll
            for (int r = 0; r < 4; r++)
                hr[r] = sm + OFF_H2 + (lane + 32 * r) * SH + ch * 20;
#pragma unroll
            for (int kq = 0; kq < 20; kq += 4) {
                float hv[4][4];
#pragma unroll
                for (int r = 0; r < 4; r++) {
                    float4 t = *(const float4*)(hr[r] + kq);
                    hv[r][0] = t.x; hv[r][1] = t.y; hv[r][2] = t.z; hv[r][3] = t.w;
                }
#pragma unroll
                for (int q = 0; q < 4; q++) {
                    const float* wrow = wb + (kq + q) * NOUT + cw;
                    ull wy = *(const ull*)(wrow + 14);
                    ulonglong2 w3 = *(const ulonglong2*)(wrow + 16);
                    ulonglong2 w4 = *(const ulonglong2*)(wrow + 20);
#pragma unroll
                    for (int r = 0; r < 4; r++) {
                        ull xa = pk2(hv[r][q], hv[r][q]);
                        By[r]     = ffma2(xa, wy,   By[r]);
                        B[r][0].x = ffma2(xa, w3.x, B[r][0].x);
                        B[r][0].y = ffma2(xa, w3.y, B[r][0].y);
                        B[r][1].x = ffma2(xa, w4.x, B[r][1].x);
                        B[r][1].y = ffma2(xa, w4.y, B[r][1].y);
                    }
                }
            }
            CP_WAIT(0);
            __syncthreads();
        }
        // pass-1 epilogue: segments 2,3 -> one-hot -> global
#pragma unroll
        for (int r = 0; r < 4; r++) {
            float v[10];
            upk2(By[r], v[0], v[1]);
            upk4(B[r][0], v + 2); upk4(B[r][1], v + 6);
            int row = lane + 32 * r;
            const float* g = gum + (size_t)(row0 + row) * (KD * 5) + warp * 20;
            float2 g0 = *(const float2*)(g + 10);
            float4 g1 = *(const float4*)(g + 12);
            float4 g2 = *(const float4*)(g + 16);
            float gf[10] = {g0.x, g0.y, g1.x, g1.y, g1.z, g1.w, g2.x, g2.y, g2.z, g2.w};
            float ov[10];
            seg_onehot(v,     gf,     ov);
            seg_onehot(v + 5, gf + 5, ov + 5);
            float* op = out + (size_t)(row0 + row) * NOUT + KD + warp * 20;
            float2 o0 = {ov[0], ov[1]};
            float4 o1 = {ov[2], ov[3], ov[4], ov[5]};
            float4 o2 = {ov[6], ov[7], ov[8], ov[9]};
            *(float2*)(op + 10) = o0;
            *(float4*)(op + 12) = o1;
            *(float4*)(op + 16) = o2;
        }
    }
    // last chunk's __syncthreads() ordered SY1 writes (pass 0) before reads below

    // ---- y1 softmax: 8 threads per row, 64 rows per iter x 2 ----
#pragma unroll
    for (int it = 0; it < 2; it++) {
        int row = it * 64 + (tid >> 3);
        int sub = tid & 7;
        const float* yr = sm + OFF_SY1 + row * SY + sub * 8;
        float4 v0 = *(const float4*)yr;
        float4 v1 = *(const float4*)(yr + 4);
        float vv[8] = {v0.x, v0.y, v0.z, v0.w, v1.x, v1.y, v1.z, v1.w};
        float mx = vv[0];
#pragma unroll
        for (int j = 1; j < 8; j++) mx = fmaxf(mx, vv[j]);
#pragma unroll
        for (int d = 1; d < 8; d <<= 1) mx = fmaxf(mx, __shfl_xor_sync(0xFFFFFFFFu, mx, d));
        float s = 0.0f;
#pragma unroll
        for (int j = 0; j < 8; j++) { vv[j] = my_expf(fmaxf(vv[j] - mx, -80.0f)); s += vv[j]; }
#pragma unroll
        for (int d = 1; d < 8; d <<= 1) s += __shfl_xor_sync(0xFFFFFFFFu, s, d);
        float rs = __frcp_rn(s);
        float* og = out + (size_t)(row0 + row) * NOUT + sub * 8;
        float4 o0 = {vv[0] * rs, vv[1] * rs, vv[2] * rs, vv[3] * rs};
        float4 o1 = {vv[4] * rs, vv[5] * rs, vv[6] * rs, vv[7] * rs};
        *(float4*)og = o0;
        *(float4*)(og + 4) = o1;
    }
}

extern "C" void kernel_launch(void* const* d_in, const int* in_sizes, int n_in,
                              void* d_out, int out_size) {
    const float* x   = (const float*)d_in[0];
    const float* W1  = (const float*)d_in[1];
    const float* b1  = (const float*)d_in[2];
    const float* W4  = (const float*)d_in[3];
    const float* b4  = (const float*)d_in[4];
    const float* W2  = (const float*)d_in[5];
    const float* b2  = (const float*)d_in[6];
    const float* gum = (const float*)d_in[7];
    float* out = (float*)d_out;

    int B = in_sizes[0] / KD;
    int grid = B / TM;

    cudaFuncSetAttribute(fused_mlp_gumbel,
                         cudaFuncAttributeMaxDynamicSharedMemorySize, SMEM_BYTES);
    fused_mlp_gumbel<<<grid, THREADS, SMEM_BYTES>>>(x, W1, b1, W4, b4, W2, b2, gum, out);
}

// round 17
// speedup vs baseline: 1.0516x; 1.0516x over previous
#include <cuda_runtime.h>
#include <cstdint>
#include <cstddef>

typedef unsigned long long ull;

#define THREADS 512
#define TM      128
#define KD      64
#define H       100
#define HP      128
#define NOUT    384
#define SXS     68    // x row stride
#define SH      100   // h row stride
#define SY      68    // y1 staging stride

// shared memory float offsets
#define OFF_H1   0                    // 128*100 = 12800 (dead after GEMM B -> SY1)
#define OFF_H2   12800                // 12800
#define OFF_W4   25600                // 100*128 = 12800
#define OFF_POOL 38400                // pool
#define OFF_X    OFF_POOL             // 128*68 = 8704   (phase A)
#define OFF_W1   (OFF_POOL + 8704)    // 64*128 = 8192   (phase A)
#define OFF_W2B  OFF_POOL             // 2 x 7680 = 15360 (phase C dbuf)
#define OFF_SY1  OFF_H1               // 128*68 = 8704   (epilogue)
#define OFF_B1   55296                // 128
#define OFF_B4   55424                // 128
#define OFF_B2   55552                // 384 (permuted)
#define SM_FLOATS 55936
#define SMEM_BYTES (SM_FLOATS * 4)    // 223744

__device__ __forceinline__ ull pk2(float lo, float hi) {
    ull r; asm("mov.b64 %0,{%1,%2};" : "=l"(r) : "f"(lo), "f"(hi)); return r;
}
__device__ __forceinline__ void upk2(ull v, float& lo, float& hi) {
    asm("mov.b64 {%0,%1},%2;" : "=f"(lo), "=f"(hi) : "l"(v));
}
__device__ __forceinline__ ull ffma2(ull a, ull b, ull c) {
    ull d; asm("fma.rn.f32x2 %0,%1,%2,%3;" : "=l"(d) : "l"(a), "l"(b), "l"(c)); return d;
}
__device__ __forceinline__ void upk4(ulonglong2 v, float* o) {
    upk2(v.x, o[0], o[1]); upk2(v.y, o[2], o[3]);
}

__device__ __forceinline__ void cp16(uint32_t dst, const void* src) {
    asm volatile("cp.async.cg.shared.global [%0], [%1], 16;" :: "r"(dst), "l"(src));
}
#define CP_COMMIT() asm volatile("cp.async.commit_group;")
#define CP_WAIT(n)  asm volatile("cp.async.wait_group %0;" :: "n"(n))

// accurate exp, fast-math-proof (no MUFU)
__device__ __forceinline__ float my_expf(float z) {
    float kf = rintf(z * 1.4426950408889634f);
    float r  = fmaf(kf, -0.693145751953125f, z);
    r        = fmaf(kf, -1.42860677e-6f,     r);
    float p  = 1.9841270e-4f;
    p = fmaf(p, r, 1.3888889e-3f);
    p = fmaf(p, r, 8.3333338e-3f);
    p = fmaf(p, r, 4.1666668e-2f);
    p = fmaf(p, r, 1.6666667e-1f);
    p = fmaf(p, r, 0.5f);
    p = fmaf(p, r, 1.0f);
    p = fmaf(p, r, 1.0f);
    int ik = (int)kf;
    return p * __int_as_float((ik + 127) << 23);
}
__device__ __forceinline__ float my_tanhf(float x) {
    float ax = fminf(fabsf(x), 10.0f);
    float e  = my_expf(2.0f * ax);
    float rc = __frcp_rn(e + 1.0f);
    float th = fmaf(-2.0f, rc, 1.0f);
    return (x < 0.0f) ? -th : th;
}

// GEMM-C permuted column index: warp w owns [24w,24w+24) =
//   y1 cols 4w..4w+3, then y2 cols 20w..20w+19 (4 full segments, in order)
__device__ __forceinline__ int permC(int c) {
    if (c < KD) return (c >> 2) * 24 + (c & 3);
    int cc = c - KD;
    return (cc / 20) * 24 + 4 + (cc % 20);
}

// one-hot argmax of 5 logits v[]+g[] -> o[0..4]
__device__ __forceinline__ void seg_onehot(const float* v, const float* g, float* o) {
    float best = v[0] + g[0];
    int arg = 0;
#pragma unroll
    for (int m = 1; m < 5; m++) {
        float val = v[m] + g[m];
        if (val > best) { best = val; arg = m; }
    }
#pragma unroll
    for (int m = 0; m < 5; m++) o[m] = (m == arg) ? 1.0f : 0.0f;
}

__global__ void __launch_bounds__(THREADS, 1)
fused_mlp_gumbel(const float* __restrict__ x,  const float* __restrict__ W1,
                 const float* __restrict__ b1, const float* __restrict__ W4,
                 const float* __restrict__ b4, const float* __restrict__ W2,
                 const float* __restrict__ b2, const float* __restrict__ gum,
                 float* __restrict__ out)
{
    extern __shared__ float sm[];
    const int tid  = threadIdx.x;
    const int warp = tid >> 5;
    const int lane = tid & 31;
    const int row0 = blockIdx.x * TM;
    const uint32_t smb = (uint32_t)__cvta_generic_to_shared(sm);

    // ---- group0: x tile + W1 via cp.async ----
    {
        const float4* xg = (const float4*)(x + (size_t)row0 * KD);
        for (int i = tid; i < TM * KD / 4; i += THREADS) {
            int r = i >> 4, c = i & 15;
            cp16(smb + (uint32_t)(OFF_X + r * SXS + c * 4) * 4, xg + i);
        }
        for (int i = tid; i < KD * 25; i += THREADS) {
            int k = i / 25, c = i - k * 25;
            cp16(smb + (uint32_t)(OFF_W1 + k * HP + c * 4) * 4, W1 + k * H + c * 4);
        }
    }
    CP_COMMIT();
    // ---- group1: W4 via cp.async (consumed after GEMM A) ----
    for (int i = tid; i < H * 25; i += THREADS) {
        int k = i / 25, c = i - k * 25;
        cp16(smb + (uint32_t)(OFF_W4 + k * HP + c * 4) * 4, W4 + k * H + c * 4);
    }
    CP_COMMIT();

    // ---- zero pads + biases (plain stores, disjoint bytes from cp.async dsts) ----
    for (int i = tid; i < KD * (HP - H); i += THREADS) {
        int k = i / 28, c = H + (i - k * 28);
        sm[OFF_W1 + k * HP + c] = 0.0f;
    }
    for (int i = tid; i < H * (HP - H); i += THREADS) {
        int k = i / 28, c = H + (i - k * 28);
        sm[OFF_W4 + k * HP + c] = 0.0f;
    }
    for (int i = tid; i < HP; i += THREADS) {
        sm[OFF_B1 + i] = (i < H) ? b1[i] : 0.0f;
        sm[OFF_B4 + i] = (i < H) ? b4[i] : 0.0f;
    }
    for (int i = tid; i < NOUT; i += THREADS) sm[OFF_B2 + permC(i)] = b2[i];

    CP_WAIT(1);          // x + W1 landed (W4 may still be in flight)
    __syncthreads();

    // ---- GEMM A: h1 = tanh(x @ W1 + b1), 4 rows x 8 cols per thread ----
    {
        const int c0 = warp * 8;
        ulonglong2 b01 = *(const ulonglong2*)(sm + OFF_B1 + c0);
        ulonglong2 b23 = *(const ulonglong2*)(sm + OFF_B1 + c0 + 4);
        ulonglong2 a[4][2];
#pragma unroll
        for (int r = 0; r < 4; r++) { a[r][0] = b01; a[r][1] = b23; }
        const float* xr[4];
#pragma unroll
        for (int r = 0; r < 4; r++) xr[r] = sm + OFF_X + (lane + 32 * r) * SXS;
#pragma unroll 4
        for (int k4 = 0; k4 < KD; k4 += 4) {
            float hv[4][4];
#pragma unroll
            for (int r = 0; r < 4; r++) {
                float4 t = *(const float4*)(xr[r] + k4);
                hv[r][0] = t.x; hv[r][1] = t.y; hv[r][2] = t.z; hv[r][3] = t.w;
            }
#pragma unroll
            for (int q = 0; q < 4; q++) {
                const ulonglong2* wp = (const ulonglong2*)(sm + OFF_W1 + (k4 + q) * HP + c0);
                ulonglong2 w0 = wp[0], w1 = wp[1];
#pragma unroll
                for (int r = 0; r < 4; r++) {
                    ull xa = pk2(hv[r][q], hv[r][q]);
                    a[r][0].x = ffma2(xa, w0.x, a[r][0].x);
                    a[r][0].y = ffma2(xa, w0.y, a[r][0].y);
                    a[r][1].x = ffma2(xa, w1.x, a[r][1].x);
                    a[r][1].y = ffma2(xa, w1.y, a[r][1].y);
                }
            }
        }
#pragma unroll
        for (int r = 0; r < 4; r++) {
            float v[8]; upk4(a[r][0], v); upk4(a[r][1], v + 4);
            float* hp = sm + OFF_H1 + (lane + 32 * r) * SH + c0;
            if (c0 + 8 <= H) {
                float4 lo = {my_tanhf(v[0]), my_tanhf(v[1]), my_tanhf(v[2]), my_tanhf(v[3])};
                float4 hi = {my_tanhf(v[4]), my_tanhf(v[5]), my_tanhf(v[6]), my_tanhf(v[7])};
                *(float4*)hp = lo; *(float4*)(hp + 4) = hi;
            } else if (c0 < H) {
                float4 lo = {my_tanhf(v[0]), my_tanhf(v[1]), my_tanhf(v[2]), my_tanhf(v[3])};
                *(float4*)hp = lo;
            }
        }
    }
    CP_WAIT(0);          // W4 landed
    __syncthreads();     // h1 visible; X/W1 region dead

    // ---- issue W2 chunk 0 -> buf0 (permuted 16B blocks), in flight during GEMM B ----
    for (int i = tid; i < 1920; i += THREADS) {
        int k = i / 96, c4 = (i - k * 96) * 4;
        int p = permC(c4);
        cp16(smb + (uint32_t)(OFF_W2B + k * NOUT + p) * 4, W2 + (size_t)k * NOUT + c4);
    }
    CP_COMMIT();

    // ---- GEMM B: h2 = tanh(h1 @ W4 + b4) ----
    {
        const int c0 = warp * 8;
        ulonglong2 b01 = *(const ulonglong2*)(sm + OFF_B4 + c0);
        ulonglong2 b23 = *(const ulonglong2*)(sm + OFF_B4 + c0 + 4);
        ulonglong2 a[4][2];
#pragma unroll
        for (int r = 0; r < 4; r++) { a[r][0] = b01; a[r][1] = b23; }
        const float* hr[4];
#pragma unroll
        for (int r = 0; r < 4; r++) hr[r] = sm + OFF_H1 + (lane + 32 * r) * SH;
#pragma unroll 5
        for (int k4 = 0; k4 < H; k4 += 4) {
            float hv[4][4];
#pragma unroll
            for (int r = 0; r < 4; r++) {
                float4 t = *(const float4*)(hr[r] + k4);
                hv[r][0] = t.x; hv[r][1] = t.y; hv[r][2] = t.z; hv[r][3] = t.w;
            }
#pragma unroll
            for (int q = 0; q < 4; q++) {
                const ulonglong2* wp = (const ulonglong2*)(sm + OFF_W4 + (k4 + q) * HP + c0);
                ulonglong2 w0 = wp[0], w1 = wp[1];
#pragma unroll
                for (int r = 0; r < 4; r++) {
                    ull xa = pk2(hv[r][q], hv[r][q]);
                    a[r][0].x = ffma2(xa, w0.x, a[r][0].x);
                    a[r][0].y = ffma2(xa, w0.y, a[r][0].y);
                    a[r][1].x = ffma2(xa, w1.x, a[r][1].x);
                    a[r][1].y = ffma2(xa, w1.y, a[r][1].y);
                }
            }
        }
#pragma unroll
        for (int r = 0; r < 4; r++) {
            float v[8]; upk4(a[r][0], v); upk4(a[r][1], v + 4);
            float* hp = sm + OFF_H2 + (lane + 32 * r) * SH + c0;
            if (c0 + 8 <= H) {
                float4 lo = {my_tanhf(v[0]), my_tanhf(v[1]), my_tanhf(v[2]), my_tanhf(v[3])};
                float4 hi = {my_tanhf(v[4]), my_tanhf(v[5]), my_tanhf(v[6]), my_tanhf(v[7])};
                *(float4*)hp = lo; *(float4*)(hp + 4) = hi;
            } else if (c0 < H) {
                float4 lo = {my_tanhf(v[0]), my_tanhf(v[1]), my_tanhf(v[2]), my_tanhf(v[3])};
                *(float4*)hp = lo;
            }
        }
    }
    CP_WAIT(0);          // chunk0 landed
    __syncthreads();     // h2 visible; H1 region dead

    // =====================================================================
    // GEMM C pass 0: perm cols cw..cw+13 = 4 y1 cols + segments 0,1
    // =====================================================================
    const int cw = warp * 24;
    {
        ulonglong2 A[4][3]; ull Ax[4];
        {
            const float* bb = sm + OFF_B2 + cw;
            ulonglong2 c0v = *(const ulonglong2*)bb;
            ulonglong2 c1v = *(const ulonglong2*)(bb + 4);
            ulonglong2 c2v = *(const ulonglong2*)(bb + 8);
            ull cxv = *(const ull*)(bb + 12);
#pragma unroll
            for (int r = 0; r < 4; r++) { A[r][0] = c0v; A[r][1] = c1v; A[r][2] = c2v; Ax[r] = cxv; }
        }
#pragma unroll 1
        for (int ch = 0; ch < 5; ch++) {
            int gi = ch, buf = gi & 1;
            {   // prefetch next chunk (always exists for gi<9)
                int nch = (gi + 1) % 5, nbuf = (gi + 1) & 1;
                for (int i = tid; i < 1920; i += THREADS) {
                    int k = i / 96, c4 = (i - k * 96) * 4;
                    int p = permC(c4);
                    cp16(smb + (uint32_t)(OFF_W2B + nbuf * 7680 + k * NOUT + p) * 4,
                         W2 + (size_t)(nch * 20 + k) * NOUT + c4);
                }
                CP_COMMIT();
            }
            const float* wb = sm + OFF_W2B + buf * 7680;
            const float* hr[4];
#pragma unroll
            for (int r = 0; r < 4; r++)
                hr[r] = sm + OFF_H2 + (lane + 32 * r) * SH + ch * 20;
#pragma unroll
            for (int kq = 0; kq < 20; kq += 4) {
                float hv[4][4];
#pragma unroll
                for (int r = 0; r < 4; r++) {
                    float4 t = *(const float4*)(hr[r] + kq);
                    hv[r][0] = t.x; hv[r][1] = t.y; hv[r][2] = t.z; hv[r][3] = t.w;
                }
#pragma unroll
                for (int q = 0; q < 4; q++) {
                    const float* wrow = wb + (kq + q) * NOUT + cw;
                    ulonglong2 w0 = *(const ulonglong2*)wrow;
                    ulonglong2 w1 = *(const ulonglong2*)(wrow + 4);
                    ulonglong2 w2 = *(const ulonglong2*)(wrow + 8);
                    ull wx = *(const ull*)(wrow + 12);
#pragma unroll
                    for (int r = 0; r < 4; r++) {
                        ull xa = pk2(hv[r][q], hv[r][q]);
                        A[r][0].x = ffma2(xa, w0.x, A[r][0].x);
                        A[r][0].y = ffma2(xa, w0.y, A[r][0].y);
                        A[r][1].x = ffma2(xa, w1.x, A[r][1].x);
                        A[r][1].y = ffma2(xa, w1.y, A[r][1].y);
                        A[r][2].x = ffma2(xa, w2.x, A[r][2].x);
                        A[r][2].y = ffma2(xa, w2.y, A[r][2].y);
                        Ax[r]     = ffma2(xa, wx,   Ax[r]);
                    }
                }
            }
            CP_WAIT(0);
            __syncthreads();
        }
        // pass-0 epilogue: y1 logits -> smem; segments 0,1 -> one-hot -> global
#pragma unroll
        for (int r = 0; r < 4; r++) {
            float v[14];
            upk4(A[r][0], v); upk4(A[r][1], v + 4); upk4(A[r][2], v + 8);
            upk2(Ax[r], v[12], v[13]);
            int row = lane + 32 * r;
            float4 s0 = {v[0], v[1], v[2], v[3]};
            *(float4*)(sm + OFF_SY1 + row * SY + warp * 4) = s0;

            const float* g = gum + (size_t)(row0 + row) * (KD * 5) + warp * 20;
            float4 g0 = *(const float4*)g;
            float4 g1 = *(const float4*)(g + 4);
            float2 g2 = *(const float2*)(g + 8);
            float gf[10] = {g0.x, g0.y, g0.z, g0.w, g1.x, g1.y, g1.z, g1.w, g2.x, g2.y};
            float ov[10];
            seg_onehot(v + 4, gf,     ov);
            seg_onehot(v + 9, gf + 5, ov + 5);
            float* op = out + (size_t)(row0 + row) * NOUT + KD + warp * 20;
            float4 o0 = {ov[0], ov[1], ov[2], ov[3]};
            float4 o1 = {ov[4], ov[5], ov[6], ov[7]};
            float2 o2 = {ov[8], ov[9]};
            *(float4*)op = o0;
            *(float4*)(op + 4) = o1;
            *(float2*)(op + 8) = o2;
        }
    }

    // =====================================================================
    // GEMM C pass 1: perm cols cw+14..cw+23 = segments 2,3
    // =====================================================================
    {
        ull By[4]; ulonglong2 B[4][2];
        {
            const float* bb = sm + OFF_B2 + cw;
            ull cyv = *(const ull*)(bb + 14);
            ulonglong2 c3v = *(const ulonglong2*)(bb + 16);
            ulonglong2 c4v = *(const ulonglong2*)(bb + 20);
#pragma unroll
            for (int r = 0; r < 4; r++) { By[r] = cyv; B[r][0] = c3v; B[r][1] = c4v; }
        }
#pragma unroll 1
        for (int ch = 0; ch < 5; ch++) {
            int gi = 5 + ch, buf = gi & 1;
            if (gi < 9) {
                int nch = (gi + 1) % 5, nbuf = (gi + 1) & 1;
                for (int i = tid; i < 1920; i += THREADS) {
                    int k = i / 96, c4 = (i - k * 96) * 4;
                    int p = permC(c4);
                    cp16(smb + (uint32_t)(OFF_W2B + nbuf * 7680 + k * NOUT + p) * 4,
                         W2 + (size_t)(nch * 20 + k) * NOUT + c4);
                }
                CP_COMMIT();
            }
            const float* wb = sm + OFF_W2B + buf * 7680;
            const float* hr[4];
#pragma unroll
            for (int r = 0; r < 4; r++)
                hr[r] = sm + OFF_H2 + (lane + 32 * r) * SH + ch * 20;
#pragma unroll
            for (int kq = 0; kq < 20; kq += 4) {
                float hv[4][4];
#pragma unroll
                for (int r = 0; r < 4; r++) {
                    float4 t = *(const float4*)(hr[r] + kq);
                    hv[r][0] = t.x; hv[r][1] = t.y; hv[r][2] = t.z; hv[r][3] = t.w;
                }
#pragma unroll
                for (int q = 0; q < 4; q++) {
                    const float* wrow = wb + (kq + q) * NOUT + cw;
                    ull wy = *(const ull*)(wrow + 14);
                    ulonglong2 w3 = *(const ulonglong2*)(wrow + 16);
                    ulonglong2 w4 = *(const ulonglong2*)(wrow + 20);
#pragma unroll
                    for (int r = 0; r < 4; r++) {
                        ull xa = pk2(hv[r][q], hv[r][q]);
                        By[r]     = ffma2(xa, wy,   By[r]);
                        B[r][0].x = ffma2(xa, w3.x, B[r][0].x);
                        B[r][0].y = ffma2(xa, w3.y, B[r][0].y);
                        B[r][1].x = ffma2(xa, w4.x, B[r][1].x);
                        B[r][1].y = ffma2(xa, w4.y, B[r][1].y);
                    }
                }
            }
            CP_WAIT(0);
            __syncthreads();
        }
        // pass-1 epilogue: segments 2,3 -> one-hot -> global
#pragma unroll
        for (int r = 0; r < 4; r++) {
            float v[10];
            upk2(By[r], v[0], v[1]);
            upk4(B[r][0], v + 2); upk4(B[r][1], v + 6);
            int row = lane + 32 * r;
            const float* g = gum + (size_t)(row0 + row) * (KD * 5) + warp * 20;
            float2 g0 = *(const float2*)(g + 10);
            float4 g1 = *(const float4*)(g + 12);
            float4 g2 = *(const float4*)(g + 16);
            float gf[10] = {g0.x, g0.y, g1.x, g1.y, g1.z, g1.w, g2.x, g2.y, g2.z, g2.w};
            float ov[10];
            seg_onehot(v,     gf,     ov);
            seg_onehot(v + 5, gf + 5, ov + 5);
            float* op = out + (size_t)(row0 + row) * NOUT + KD + warp * 20;
            float2 o0 = {ov[0], ov[1]};
            float4 o1 = {ov[2], ov[3], ov[4], ov[5]};
            float4 o2 = {ov[6], ov[7], ov[8], ov[9]};
            *(float2*)(op + 10) = o0;
            *(float4*)(op + 12) = o1;
            *(float4*)(op + 16) = o2;
        }
    }
    // last chunk's __syncthreads() ordered SY1 writes (pass 0) before reads below

    // ---- y1 softmax: 8 threads per row, 64 rows per iter x 2 ----
#pragma unroll
    for (int it = 0; it < 2; it++) {
        int row = it * 64 + (tid >> 3);
        int sub = tid & 7;
        const float* yr = sm + OFF_SY1 + row * SY + sub * 8;
        float4 v0 = *(const float4*)yr;
        float4 v1 = *(const float4*)(yr + 4);
        float vv[8] = {v0.x, v0.y, v0.z, v0.w, v1.x, v1.y, v1.z, v1.w};
        float mx = vv[0];
#pragma unroll
        for (int j = 1; j < 8; j++) mx = fmaxf(mx, vv[j]);
#pragma unroll
        for (int d = 1; d < 8; d <<= 1) mx = fmaxf(mx, __shfl_xor_sync(0xFFFFFFFFu, mx, d));
        float s = 0.0f;
#pragma unroll
        for (int j = 0; j < 8; j++) { vv[j] = my_expf(fmaxf(vv[j] - mx, -80.0f)); s += vv[j]; }
#pragma unroll
        for (int d = 1; d < 8; d <<= 1) s += __shfl_xor_sync(0xFFFFFFFFu, s, d);
        float rs = __frcp_rn(s);
        float* og = out + (size_t)(row0 + row) * NOUT + sub * 8;
        float4 o0 = {vv[0] * rs, vv[1] * rs, vv[2] * rs, vv[3] * rs};
        float4 o1 = {vv[4] * rs, vv[5] * rs, vv[6] * rs, vv[7] * rs};
        *(float4*)og = o0;
        *(float4*)(og + 4) = o1;
    }
}

extern "C" void kernel_launch(void* const* d_in, const int* in_sizes, int n_in,
                              void* d_out, int out_size) {
    const float* x   = (const float*)d_in[0];
    const float* W1  = (const float*)d_in[1];
    const float* b1  = (const float*)d_in[2];
    const float* W4  = (const float*)d_in[3];
    const float* b4  = (const float*)d_in[4];
    const float* W2  = (const float*)d_in[5];
    const float* b2  = (const float*)d_in[6];
    const float* gum = (const float*)d_in[7];
    float* out = (float*)d_out;

    int B = in_sizes[0] / KD;
    int grid = B / TM;

    cudaFuncSetAttribute(fused_mlp_gumbel,
                         cudaFuncAttributeMaxDynamicSharedMemorySize, SMEM_BYTES);
    fused_mlp_gumbel<<<grid, THREADS, SMEM_BYTES>>>(x, W1, b1, W4, b4, W2, b2, gum, out);
}